// round 11
// baseline (speedup 1.0000x reference)
#include <cuda_runtime.h>

#define N_NODES 100000
#define N_EDGES 1600000
#define DIM 128
#define HID 16
#define NCLS 40
#define BN_EPS 1e-5f

typedef unsigned long long ull;

// ---------------- f32x2 packed-math helpers (B300 FFMA2 path) --------------
__device__ __forceinline__ ull pack2(float x, float y) {
    ull r; asm("mov.b64 %0,{%1,%2};" : "=l"(r) : "f"(x), "f"(y)); return r;
}
__device__ __forceinline__ void unpack2(ull v, float& x, float& y) {
    asm("mov.b64 {%0,%1},%2;" : "=f"(x), "=f"(y) : "l"(v));
}
__device__ __forceinline__ ull fma2(ull a, ull b, ull c) {
    ull d; asm("fma.rn.f32x2 %0,%1,%2,%3;" : "=l"(d) : "l"(a), "l"(b), "l"(c)); return d;
}
__device__ __forceinline__ ull add2(ull a, ull b) {
    ull d; asm("add.rn.f32x2 %0,%1,%2;" : "=l"(d) : "l"(a), "l"(b)); return d;
}
__device__ __forceinline__ ull shfl2(ull v, int src) {
    float lo, hi; unpack2(v, lo, hi);
    lo = __shfl_sync(0xffffffffu, lo, src);
    hi = __shfl_sync(0xffffffffu, hi, src);
    return pack2(lo, hi);
}
// ---------------- PDL primitives -------------------------------------------
__device__ __forceinline__ void pdl_wait() {
    asm volatile("griddepcontrol.wait;" ::: "memory");
}
__device__ __forceinline__ void pdl_trigger() {
    asm volatile("griddepcontrol.launch_dependents;" ::: "memory");
}

// ---------------- scratch (static device globals) ---------------------------
__device__ float  g_h1[N_NODES * HID];
__device__ float  g_s1[N_NODES * HID];
__device__ float  g_agg[N_NODES * HID];
__device__ double g_M3[3][HID * HID];
__device__ double g_sum3[3][HID];
__device__ float  g_scale3[3][DIM];
__device__ float  g_shift3[3][DIM];
__device__ unsigned int g_cnt3[3];
__device__ int    g_row_ptr[N_NODES + 1];

#define TB 256
#define NODE_BLK ((N_NODES + TB - 1) / TB)          // 391
#define RP_BLK   ((N_NODES + 1 + TB - 1) / TB)      // 391
#define N_PAIRS  (N_NODES / 2)                      // 50000
#define SPMM_BLK (N_PAIRS / 8)                      // 6250 (warp = pair, exact)
#define STATS_BLK 592                               // strided stats variant

// ---------------- fused: row_ptr build + stats zero + x@W1 ------------------
__global__ void prolog_kernel(const int* __restrict__ row, const float* __restrict__ x,
                              const float* __restrict__ W, float* __restrict__ y) {
    if (blockIdx.x >= NODE_BLK) {
        int t = threadIdx.x;
        if (blockIdx.x == NODE_BLK) {
            if (t < HID * HID) { g_M3[0][t] = 0.0; g_M3[1][t] = 0.0; g_M3[2][t] = 0.0; }
            if (t < HID) { g_sum3[0][t] = 0.0; g_sum3[1][t] = 0.0; g_sum3[2][t] = 0.0; }
            if (t < 3) g_cnt3[t] = 0u;
        }
        int i = (blockIdx.x - NODE_BLK) * TB + t;
        if (i <= N_NODES) {
            int lo = 0, hi = N_EDGES;
            while (lo < hi) {
                int mid = (lo + hi) >> 1;
                if (row[mid] < i) lo = mid + 1; else hi = mid;
            }
            g_row_ptr[i] = lo;
        }
        pdl_trigger();
        return;
    }
    __shared__ __align__(16) float Ws[DIM * HID];
    for (int i = threadIdx.x; i < DIM * HID; i += TB) Ws[i] = W[i];
    __syncthreads();
    int n = blockIdx.x * TB + threadIdx.x;
    if (n < N_NODES) {
        ull acc2[8];
        #pragma unroll
        for (int j = 0; j < 8; j++) acc2[j] = 0ull;
        const float4* xr = reinterpret_cast<const float4*>(x + (size_t)n * DIM);
        #pragma unroll 4
        for (int d4 = 0; d4 < DIM / 4; d4++) {
            float4 xv = xr[d4];
            #pragma unroll
            for (int dd = 0; dd < 4; dd++) {
                float xd = (&xv.x)[dd];
                ull xb = pack2(xd, xd);
                const ulonglong2* wr =
                    reinterpret_cast<const ulonglong2*>(&Ws[(d4 * 4 + dd) * HID]);
                #pragma unroll
                for (int p = 0; p < 4; p++) {
                    ulonglong2 w = wr[p];
                    acc2[p * 2 + 0] = fma2(xb, w.x, acc2[p * 2 + 0]);
                    acc2[p * 2 + 1] = fma2(xb, w.y, acc2[p * 2 + 1]);
                }
            }
        }
        ull* yr = reinterpret_cast<ull*>(y + (size_t)n * HID);
        #pragma unroll
        for (int j = 0; j < 8; j++) yr[j] = acc2[j];
    }
    pdl_trigger();
}

// ---------------- 16-wide SpMM (v3 core): warp per row pair -----------------
// STATS: strided grid; fuses BN sufficient statistics; LAST block computes
// the BN affine (scale/shift) so fused_bn_gemm stays lean.
template<bool RELU, bool STATS>
__global__ void spmm16(const float* __restrict__ h, const float* __restrict__ vals,
                       const int* __restrict__ col, const float* __restrict__ bias,
                       float* __restrict__ out, double* __restrict__ gM,
                       double* __restrict__ gSum, const float* __restrict__ W2,
                       const float* __restrict__ gamma, const float* __restrict__ beta,
                       float* __restrict__ gScale, float* __restrict__ gShift,
                       unsigned int* __restrict__ cnt) {
    __shared__ float sM[HID * HID];
    __shared__ float sSum[HID];
    int t = threadIdx.x;
    if (STATS) {
        if (t < HID * HID) sM[t] = 0.f;
        if (t < HID) sSum[t] = 0.f;
        __syncthreads();
    }
    pdl_wait();
    int lane = t & 31;
    int warp = t >> 5;
    int q = lane & 7;
    int sub = lane >> 3;
    const ull* h8 = reinterpret_cast<const ull*>(h);
    float b0 = 0.f, b1 = 0.f;
    if (RELU) { b0 = bias[2 * q]; b1 = bias[2 * q + 1]; }

    ull mAcc[4];
    ull sumAcc = 0ull;
    #pragma unroll
    for (int s = 0; s < 4; s++) mAcc[s] = 0ull;

    int p0 = blockIdx.x * 8 + warp;
    int pstep = STATS ? (STATS_BLK * 8) : (SPMM_BLK * 8 + 1);
    for (int p = p0; p < N_PAIRS; p += pstep) {
        int r0 = p * 2;
        int a0 = g_row_ptr[r0];
        int a1 = g_row_ptr[r0 + 1];
        int a2 = g_row_ptr[r0 + 2];
        int len = a2 - a0;
        ull accA = 0ull, accB = 0ull;
        for (int off = sub * 8; off < len; off += 32) {
            #pragma unroll
            for (int i = 0; i < 8; i++) {
                int o = off + i;
                bool valid = (o < len);
                int idx = valid ? (a0 + o) : (a2 - 1);
                float v = vals[idx];
                if (!valid) v = 0.f;
                int c = col[idx];
                ull hv = h8[(size_t)c * 8 + q];
                float vA = ((a0 + o) < a1) ? v : 0.f;
                float vB = v - vA;
                accA = fma2(pack2(vA, vA), hv, accA);
                accB = fma2(pack2(vB, vB), hv, accB);
            }
        }
        accA = add2(accA, __shfl_xor_sync(0xffffffffu, accA, 8));
        accA = add2(accA, __shfl_xor_sync(0xffffffffu, accA, 16));
        accB = add2(accB, __shfl_xor_sync(0xffffffffu, accB, 8));
        accB = add2(accB, __shfl_xor_sync(0xffffffffu, accB, 16));
        if (sub == 0) {
            float x0, x1, y0, y1;
            unpack2(accA, x0, x1);
            unpack2(accB, y0, y1);
            if (RELU) {
                x0 = fmaxf(x0 + b0, 0.f); x1 = fmaxf(x1 + b1, 0.f);
                y0 = fmaxf(y0 + b0, 0.f); y1 = fmaxf(y1 + b1, 0.f);
            }
            float2* o2 = reinterpret_cast<float2*>(out);
            o2[(size_t)r0 * 8 + q]       = make_float2(x0, x1);
            o2[(size_t)(r0 + 1) * 8 + q] = make_float2(y0, y1);
        }
        if (STATS) {
            sumAcc = add2(sumAcc, add2(accA, accB));
            int srcj = lane >> 2;
            int klane = (lane & 1) * 4;
            ull ja2 = shfl2(accA, srcj);
            ull jb2 = shfl2(accB, srcj);
            float jlA, jhA, jlB, jhB;
            unpack2(ja2, jlA, jhA);
            unpack2(jb2, jlB, jhB);
            float ajA = (lane & 2) ? jhA : jlA;
            float ajB = (lane & 2) ? jhB : jlB;
            ull ajA2 = pack2(ajA, ajA);
            ull ajB2 = pack2(ajB, ajB);
            #pragma unroll
            for (int s = 0; s < 4; s++) {
                ull kA = shfl2(accA, klane + s);
                ull kB = shfl2(accB, klane + s);
                mAcc[s] = fma2(ajA2, kA, mAcc[s]);
                mAcc[s] = fma2(ajB2, kB, mAcc[s]);
            }
        }
    }
    pdl_trigger();
    if (!STATS) return;
    {
        int j = lane >> 1;
        int k0 = (lane & 1) * 8;
        #pragma unroll
        for (int s = 0; s < 4; s++) {
            float lo, hi;
            unpack2(mAcc[s], lo, hi);
            atomicAdd(&sM[j * HID + k0 + 2 * s],     lo);
            atomicAdd(&sM[j * HID + k0 + 2 * s + 1], hi);
        }
        if (sub == 0) {
            float lo, hi;
            unpack2(sumAcc, lo, hi);
            atomicAdd(&sSum[2 * q],     lo);
            atomicAdd(&sSum[2 * q + 1], hi);
        }
        __syncthreads();
        if (t < HID * HID) atomicAdd(&gM[t], (double)sM[t]);
        if (t < HID) atomicAdd(&gSum[t], (double)sSum[t]);
    }
    // ---- last block computes BN affine (scale/shift) ----
    __threadfence();
    __shared__ unsigned int sIsLast;
    if (t == 0) sIsLast = (atomicAdd(cnt, 1u) == STATS_BLK - 1) ? 1u : 0u;
    __syncthreads();
    if (!sIsLast) return;
    __shared__ double Ss[HID];
    if (t < HID) Ss[t] = gSum[t];
    __syncthreads();
    const double invN = 1.0 / (double)N_NODES;
    {
        int j2 = t >> 4, k2 = t & 15;
        sM[t] = (float)(gM[t] - Ss[j2] * Ss[k2] * invN);   // centered, fp32
    }
    __syncthreads();
    if (t < DIM) {
        float wf[HID];
        #pragma unroll
        for (int kk = 0; kk < HID; kk++) wf[kk] = W2[kk * DIM + t];
        double sn = 0.0;
        #pragma unroll
        for (int kk = 0; kk < HID; kk++) sn += Ss[kk] * (double)wf[kk];
        sn *= invN;
        float q0 = 0.f, q1 = 0.f, q2 = 0.f, q3 = 0.f;
        #pragma unroll
        for (int a = 0; a < HID; a++) {
            float wa = wf[a];
            #pragma unroll
            for (int b = 0; b < HID; b += 4) {
                q0 += sM[a * HID + b + 0] * (wa * wf[b + 0]);
                q1 += sM[a * HID + b + 1] * (wa * wf[b + 1]);
                q2 += sM[a * HID + b + 2] * (wa * wf[b + 2]);
                q3 += sM[a * HID + b + 3] * (wa * wf[b + 3]);
            }
        }
        float var = ((q0 + q1) + (q2 + q3)) * (float)invN;
        float scale = rsqrtf(fmaxf(var, 0.f) + BN_EPS) * gamma[t];
        gScale[t] = scale;
        gShift[t] = beta[t] - (float)sn * scale;   // b2 cancels in (h2-mean)
    }
}

// ---------------- fused: h1 = relu(bn(agg@W2)) @ W1next  (lean, round-7) ----
__global__ void fused_bn_gemm(const float* __restrict__ agg, const float* __restrict__ W2,
                              const float* __restrict__ W1n,
                              const float* __restrict__ gScale,
                              const float* __restrict__ gShift,
                              float* __restrict__ y) {
    __shared__ __align__(16) float W2s[HID * DIM];
    __shared__ __align__(16) float W1s[DIM * HID];
    __shared__ __align__(16) float scl[DIM];
    __shared__ __align__(16) float sft[DIM];
    for (int i = threadIdx.x; i < HID * DIM; i += TB) {
        W2s[i] = W2[i];
        W1s[i] = W1n[i];
    }
    pdl_wait();
    for (int i = threadIdx.x; i < DIM; i += TB) {
        scl[i] = gScale[i];
        sft[i] = gShift[i];
    }
    __syncthreads();
    int n = blockIdx.x * TB + threadIdx.x;
    if (n < N_NODES) {
        ull a2[HID];
        {
            const float4* ar = reinterpret_cast<const float4*>(agg + (size_t)n * HID);
            #pragma unroll
            for (int k4 = 0; k4 < 4; k4++) {
                float4 v = ar[k4];
                a2[k4*4+0] = pack2(v.x, v.x);
                a2[k4*4+1] = pack2(v.y, v.y);
                a2[k4*4+2] = pack2(v.z, v.z);
                a2[k4*4+3] = pack2(v.w, v.w);
            }
        }
        ull acc2[8];
        #pragma unroll
        for (int j = 0; j < 8; j++) acc2[j] = 0ull;
        #pragma unroll 2
        for (int cb = 0; cb < DIM; cb += 4) {
            ull t01 = 0ull, t23 = 0ull;
            const ulonglong2* w2p = reinterpret_cast<const ulonglong2*>(&W2s[cb]);
            #pragma unroll
            for (int k = 0; k < HID; k++) {
                ulonglong2 w = w2p[k * (DIM / 4)];
                t01 = fma2(a2[k], w.x, t01);
                t23 = fma2(a2[k], w.y, t23);
            }
            ulonglong2 sc = *reinterpret_cast<const ulonglong2*>(&scl[cb]);
            ulonglong2 sf = *reinterpret_cast<const ulonglong2*>(&sft[cb]);
            t01 = fma2(t01, sc.x, sf.x);
            t23 = fma2(t23, sc.y, sf.y);
            float v0, v1, v2, v3;
            unpack2(t01, v0, v1);
            unpack2(t23, v2, v3);
            v0 = fmaxf(v0, 0.f); v1 = fmaxf(v1, 0.f);
            v2 = fmaxf(v2, 0.f); v3 = fmaxf(v3, 0.f);
            ull vb[4] = { pack2(v0, v0), pack2(v1, v1), pack2(v2, v2), pack2(v3, v3) };
            #pragma unroll
            for (int c = 0; c < 4; c++) {
                const ulonglong2* w1p =
                    reinterpret_cast<const ulonglong2*>(&W1s[(cb + c) * HID]);
                #pragma unroll
                for (int p = 0; p < 4; p++) {
                    ulonglong2 w = w1p[p];
                    acc2[p * 2 + 0] = fma2(vb[c], w.x, acc2[p * 2 + 0]);
                    acc2[p * 2 + 1] = fma2(vb[c], w.y, acc2[p * 2 + 1]);
                }
            }
        }
        ull* yr = reinterpret_cast<ull*>(y + (size_t)n * HID);
        #pragma unroll
        for (int j = 0; j < 8; j++) yr[j] = acc2[j];
    }
    pdl_trigger();
}

// ---------------- out[N,40] = agg[N,16] @ W[16,40] + b  (f32x2 packed) ------
__global__ void out_gemm(const float* __restrict__ agg, const float* __restrict__ W,
                         const float* __restrict__ b, float* __restrict__ out) {
    __shared__ __align__(16) float Ws[HID * NCLS];
    __shared__ __align__(16) float bs[NCLS];
    for (int i = threadIdx.x; i < HID * NCLS; i += TB) Ws[i] = W[i];
    if (threadIdx.x < NCLS) bs[threadIdx.x] = b[threadIdx.x];
    pdl_wait();
    __syncthreads();
    int n = blockIdx.x * TB + threadIdx.x;
    if (n >= N_NODES) return;
    ull a2[HID];
    {
        const float4* ar = reinterpret_cast<const float4*>(agg + (size_t)n * HID);
        #pragma unroll
        for (int k4 = 0; k4 < 4; k4++) {
            float4 v = ar[k4];
            a2[k4*4+0] = pack2(v.x, v.x);
            a2[k4*4+1] = pack2(v.y, v.y);
            a2[k4*4+2] = pack2(v.z, v.z);
            a2[k4*4+3] = pack2(v.w, v.w);
        }
    }
    ull o2[NCLS / 2];
    const ull* bp = reinterpret_cast<const ull*>(bs);
    #pragma unroll
    for (int p = 0; p < NCLS / 2; p++) o2[p] = bp[p];
    #pragma unroll
    for (int k = 0; k < HID; k++) {
        const ull* wr = reinterpret_cast<const ull*>(&Ws[k * NCLS]);
        #pragma unroll
        for (int p = 0; p < NCLS / 2; p++)
            o2[p] = fma2(a2[k], wr[p], o2[p]);
    }
    ull* orow = reinterpret_cast<ull*>(out + (size_t)n * NCLS);
    #pragma unroll
    for (int p = 0; p < NCLS / 2; p++) orow[p] = o2[p];
}

// ---------------- PDL launch helper -----------------------------------------
#define PDL_LAUNCH(kern, grid, ...) do {                                     \
    cudaLaunchConfig_t _cfg = {};                                            \
    _cfg.gridDim = dim3((unsigned)(grid));                                   \
    _cfg.blockDim = dim3(TB);                                                \
    _cfg.stream = 0;                                                         \
    cudaLaunchAttribute _at[1];                                              \
    _at[0].id = cudaLaunchAttributeProgrammaticStreamSerialization;          \
    _at[0].val.programmaticStreamSerializationAllowed = 1;                   \
    _cfg.attrs = _at; _cfg.numAttrs = 1;                                     \
    cudaLaunchKernelEx(&_cfg, kern, __VA_ARGS__);                            \
} while (0)

// ============================================================================
extern "C" void kernel_launch(void* const* d_in, const int* in_sizes, int n_in,
                              void* d_out, int out_size) {
    const float* x     = (const float*)d_in[0];
    const float* vals  = (const float*)d_in[1];
    const float* W1    = (const float*)d_in[2];   // (3,128,16)
    const float* b1    = (const float*)d_in[3];   // (3,16)
    const float* W2    = (const float*)d_in[4];   // (3,16,128)
    const float* gamma = (const float*)d_in[6];   // (3,128)
    const float* beta  = (const float*)d_in[7];   // (3,128)
    const float* W1f   = (const float*)d_in[8];   // (128,16)
    const float* b1f   = (const float*)d_in[9];   // (16,)
    const float* W2f   = (const float*)d_in[10];  // (16,40)
    const float* b2f   = (const float*)d_in[11];  // (40,)
    const int*   row   = (const int*)d_in[12];
    const int*   col   = (const int*)d_in[13];
    float* out = (float*)d_out;
    // d_in[5] (b2) cancels inside batchnorm.

    float *p_h1, *p_s1, *p_agg, *p_scale3, *p_shift3;
    double *p_M3, *p_sum3;
    unsigned int* p_cnt3;
    cudaGetSymbolAddress((void**)&p_h1,    g_h1);
    cudaGetSymbolAddress((void**)&p_s1,    g_s1);
    cudaGetSymbolAddress((void**)&p_agg,   g_agg);
    cudaGetSymbolAddress((void**)&p_M3,    g_M3);
    cudaGetSymbolAddress((void**)&p_sum3,  g_sum3);
    cudaGetSymbolAddress((void**)&p_scale3, g_scale3);
    cudaGetSymbolAddress((void**)&p_shift3, g_shift3);
    cudaGetSymbolAddress((void**)&p_cnt3,  g_cnt3);

    prolog_kernel<<<NODE_BLK + RP_BLK, TB>>>(row, x, W1, p_h1);

    for (int i = 0; i < 3; i++) {
        double* gM = p_M3 + (size_t)i * HID * HID;
        double* gS = p_sum3 + (size_t)i * HID;
        float* gScale = p_scale3 + (size_t)i * DIM;
        float* gShift = p_shift3 + (size_t)i * DIM;
        const float* W2L = W2 + (size_t)i * HID * DIM;
        const float* Wnext = (i < 2) ? (W1 + (size_t)(i + 1) * DIM * HID) : W1f;

        PDL_LAUNCH((spmm16<true, false>), SPMM_BLK,
                   p_h1, vals, col, b1 + i * HID, p_s1,
                   (double*)nullptr, (double*)nullptr, (const float*)nullptr,
                   (const float*)nullptr, (const float*)nullptr,
                   (float*)nullptr, (float*)nullptr, (unsigned int*)nullptr);
        PDL_LAUNCH((spmm16<false, true>), STATS_BLK,
                   p_s1, vals, col, (const float*)nullptr, p_agg,
                   gM, gS, W2L, gamma + i * DIM, beta + i * DIM,
                   gScale, gShift, p_cnt3 + i);
        PDL_LAUNCH(fused_bn_gemm, NODE_BLK,
                   (const float*)p_agg, W2L, Wnext,
                   (const float*)gScale, (const float*)gShift, p_h1);
    }

    PDL_LAUNCH((spmm16<true, false>), SPMM_BLK,
               p_h1, vals, col, b1f, p_s1,
               (double*)nullptr, (double*)nullptr, (const float*)nullptr,
               (const float*)nullptr, (const float*)nullptr,
               (float*)nullptr, (float*)nullptr, (unsigned int*)nullptr);
    PDL_LAUNCH((spmm16<false, false>), SPMM_BLK,
               p_s1, vals, col, (const float*)nullptr, p_agg,
               (double*)nullptr, (double*)nullptr, (const float*)nullptr,
               (const float*)nullptr, (const float*)nullptr,
               (float*)nullptr, (float*)nullptr, (unsigned int*)nullptr);
    PDL_LAUNCH(out_gemm, NODE_BLK, (const float*)p_agg, W2f, b2f, out);
}

// round 12
// speedup vs baseline: 1.0720x; 1.0720x over previous
#include <cuda_runtime.h>

#define N_NODES 100000
#define N_EDGES 1600000
#define DIM 128
#define HID 16
#define NCLS 40
#define BN_EPS 1e-5f

typedef unsigned long long ull;

// ---------------- f32x2 packed-math helpers (B300 FFMA2 path) --------------
__device__ __forceinline__ ull pack2(float x, float y) {
    ull r; asm("mov.b64 %0,{%1,%2};" : "=l"(r) : "f"(x), "f"(y)); return r;
}
__device__ __forceinline__ void unpack2(ull v, float& x, float& y) {
    asm("mov.b64 {%0,%1},%2;" : "=f"(x), "=f"(y) : "l"(v));
}
__device__ __forceinline__ ull fma2(ull a, ull b, ull c) {
    ull d; asm("fma.rn.f32x2 %0,%1,%2,%3;" : "=l"(d) : "l"(a), "l"(b), "l"(c)); return d;
}
__device__ __forceinline__ ull add2(ull a, ull b) {
    ull d; asm("add.rn.f32x2 %0,%1,%2;" : "=l"(d) : "l"(a), "l"(b)); return d;
}
__device__ __forceinline__ ull shfl2(ull v, int src) {
    float lo, hi; unpack2(v, lo, hi);
    lo = __shfl_sync(0xffffffffu, lo, src);
    hi = __shfl_sync(0xffffffffu, hi, src);
    return pack2(lo, hi);
}

// ---------------- scratch (static device globals) ---------------------------
__device__ float  g_h1[N_NODES * HID];
__device__ float  g_s1[N_NODES * HID];
__device__ float  g_agg[N_NODES * HID];
__device__ double g_M3[3][HID * HID];
__device__ double g_sum3[3][HID];
__device__ float  g_scale3[3][DIM];
__device__ float  g_shift3[3][DIM];
__device__ unsigned int g_cnt3[3];
__device__ int    g_row_ptr[N_NODES + 1];

#define TB 256
#define FTB 128
#define NODE_BLK ((N_NODES + TB - 1) / TB)          // 391
#define RP_BLK   ((N_NODES + 1 + TB - 1) / TB)      // 391
#define FUSED_BLK ((N_NODES + 255) / 256)           // 391 (2 nodes/thread @128thr)
#define N_PAIRS  (N_NODES / 2)                      // 50000
#define SPMM_BLK (N_PAIRS / 8)                      // 6250 (warp = pair, exact)
#define STATS_BLK 592                               // strided stats variant

// ---------------- fused: row_ptr build + stats zero + x@W1 ------------------
__global__ void prolog_kernel(const int* __restrict__ row, const float* __restrict__ x,
                              const float* __restrict__ W, float* __restrict__ y) {
    if (blockIdx.x >= NODE_BLK) {
        int t = threadIdx.x;
        if (blockIdx.x == NODE_BLK) {
            if (t < HID * HID) { g_M3[0][t] = 0.0; g_M3[1][t] = 0.0; g_M3[2][t] = 0.0; }
            if (t < HID) { g_sum3[0][t] = 0.0; g_sum3[1][t] = 0.0; g_sum3[2][t] = 0.0; }
            if (t < 3) g_cnt3[t] = 0u;
        }
        int i = (blockIdx.x - NODE_BLK) * TB + t;
        if (i > N_NODES) return;
        int lo = 0, hi = N_EDGES;
        while (lo < hi) {
            int mid = (lo + hi) >> 1;
            if (row[mid] < i) lo = mid + 1; else hi = mid;
        }
        g_row_ptr[i] = lo;
        return;
    }
    __shared__ __align__(16) float Ws[DIM * HID];
    for (int i = threadIdx.x; i < DIM * HID; i += TB) Ws[i] = W[i];
    __syncthreads();
    int n = blockIdx.x * TB + threadIdx.x;
    if (n >= N_NODES) return;
    ull acc2[8];
    #pragma unroll
    for (int j = 0; j < 8; j++) acc2[j] = 0ull;
    const float4* xr = reinterpret_cast<const float4*>(x + (size_t)n * DIM);
    #pragma unroll 4
    for (int d4 = 0; d4 < DIM / 4; d4++) {
        float4 xv = xr[d4];
        #pragma unroll
        for (int dd = 0; dd < 4; dd++) {
            float xd = (&xv.x)[dd];
            ull xb = pack2(xd, xd);
            const ulonglong2* wr = reinterpret_cast<const ulonglong2*>(&Ws[(d4 * 4 + dd) * HID]);
            #pragma unroll
            for (int p = 0; p < 4; p++) {
                ulonglong2 w = wr[p];
                acc2[p * 2 + 0] = fma2(xb, w.x, acc2[p * 2 + 0]);
                acc2[p * 2 + 1] = fma2(xb, w.y, acc2[p * 2 + 1]);
            }
        }
    }
    ull* yr = reinterpret_cast<ull*>(y + (size_t)n * HID);
    #pragma unroll
    for (int j = 0; j < 8; j++) yr[j] = acc2[j];
}

// ---------------- 16-wide SpMM (v3 core): warp per row pair -----------------
// STATS: strided grid; fuses BN sufficient statistics; LAST block computes
// the BN affine (scale/shift) so fused_bn_gemm stays lean.
template<bool RELU, bool STATS>
__global__ void spmm16(const float* __restrict__ h, const float* __restrict__ vals,
                       const int* __restrict__ col, const float* __restrict__ bias,
                       float* __restrict__ out, double* __restrict__ gM,
                       double* __restrict__ gSum, const float* __restrict__ W2,
                       const float* __restrict__ gamma, const float* __restrict__ beta,
                       float* __restrict__ gScale, float* __restrict__ gShift,
                       unsigned int* __restrict__ cnt) {
    __shared__ float sM[HID * HID];
    __shared__ float sSum[HID];
    int t = threadIdx.x;
    if (STATS) {
        if (t < HID * HID) sM[t] = 0.f;
        if (t < HID) sSum[t] = 0.f;
        __syncthreads();
    }
    int lane = t & 31;
    int warp = t >> 5;
    int q = lane & 7;
    int sub = lane >> 3;
    const ull* h8 = reinterpret_cast<const ull*>(h);
    float b0 = 0.f, b1 = 0.f;
    if (RELU) { b0 = bias[2 * q]; b1 = bias[2 * q + 1]; }

    ull mAcc[4];
    ull sumAcc = 0ull;
    #pragma unroll
    for (int s = 0; s < 4; s++) mAcc[s] = 0ull;

    int p0 = blockIdx.x * 8 + warp;
    int pstep = STATS ? (STATS_BLK * 8) : (SPMM_BLK * 8 + 1);
    for (int p = p0; p < N_PAIRS; p += pstep) {
        int r0 = p * 2;
        int a0 = g_row_ptr[r0];
        int a1 = g_row_ptr[r0 + 1];
        int a2 = g_row_ptr[r0 + 2];
        int len = a2 - a0;
        ull accA = 0ull, accB = 0ull;
        for (int off = sub * 8; off < len; off += 32) {
            #pragma unroll
            for (int i = 0; i < 8; i++) {
                int o = off + i;
                bool valid = (o < len);
                int idx = valid ? (a0 + o) : (a2 - 1);
                float v = vals[idx];
                if (!valid) v = 0.f;
                int c = col[idx];
                ull hv = h8[(size_t)c * 8 + q];
                float vA = ((a0 + o) < a1) ? v : 0.f;
                float vB = v - vA;
                accA = fma2(pack2(vA, vA), hv, accA);
                accB = fma2(pack2(vB, vB), hv, accB);
            }
        }
        accA = add2(accA, __shfl_xor_sync(0xffffffffu, accA, 8));
        accA = add2(accA, __shfl_xor_sync(0xffffffffu, accA, 16));
        accB = add2(accB, __shfl_xor_sync(0xffffffffu, accB, 8));
        accB = add2(accB, __shfl_xor_sync(0xffffffffu, accB, 16));
        if (sub == 0) {
            float x0, x1, y0, y1;
            unpack2(accA, x0, x1);
            unpack2(accB, y0, y1);
            if (RELU) {
                x0 = fmaxf(x0 + b0, 0.f); x1 = fmaxf(x1 + b1, 0.f);
                y0 = fmaxf(y0 + b0, 0.f); y1 = fmaxf(y1 + b1, 0.f);
            }
            float2* o2 = reinterpret_cast<float2*>(out);
            o2[(size_t)r0 * 8 + q]       = make_float2(x0, x1);
            o2[(size_t)(r0 + 1) * 8 + q] = make_float2(y0, y1);
        }
        if (STATS) {
            sumAcc = add2(sumAcc, add2(accA, accB));
            int srcj = lane >> 2;
            int klane = (lane & 1) * 4;
            ull ja2 = shfl2(accA, srcj);
            ull jb2 = shfl2(accB, srcj);
            float jlA, jhA, jlB, jhB;
            unpack2(ja2, jlA, jhA);
            unpack2(jb2, jlB, jhB);
            float ajA = (lane & 2) ? jhA : jlA;
            float ajB = (lane & 2) ? jhB : jlB;
            ull ajA2 = pack2(ajA, ajA);
            ull ajB2 = pack2(ajB, ajB);
            #pragma unroll
            for (int s = 0; s < 4; s++) {
                ull kA = shfl2(accA, klane + s);
                ull kB = shfl2(accB, klane + s);
                mAcc[s] = fma2(ajA2, kA, mAcc[s]);
                mAcc[s] = fma2(ajB2, kB, mAcc[s]);
            }
        }
    }
    if (!STATS) return;
    {
        int j = lane >> 1;
        int k0 = (lane & 1) * 8;
        #pragma unroll
        for (int s = 0; s < 4; s++) {
            float lo, hi;
            unpack2(mAcc[s], lo, hi);
            atomicAdd(&sM[j * HID + k0 + 2 * s],     lo);
            atomicAdd(&sM[j * HID + k0 + 2 * s + 1], hi);
        }
        if (sub == 0) {
            float lo, hi;
            unpack2(sumAcc, lo, hi);
            atomicAdd(&sSum[2 * q],     lo);
            atomicAdd(&sSum[2 * q + 1], hi);
        }
        __syncthreads();
        if (t < HID * HID) atomicAdd(&gM[t], (double)sM[t]);
        if (t < HID) atomicAdd(&gSum[t], (double)sSum[t]);
    }
    // ---- last block computes BN affine (scale/shift) ----
    __threadfence();
    __shared__ unsigned int sIsLast;
    if (t == 0) sIsLast = (atomicAdd(cnt, 1u) == STATS_BLK - 1) ? 1u : 0u;
    __syncthreads();
    if (!sIsLast) return;
    __shared__ double Ss[HID];
    if (t < HID) Ss[t] = gSum[t];
    __syncthreads();
    const double invN = 1.0 / (double)N_NODES;
    {
        int j2 = t >> 4, k2 = t & 15;
        sM[t] = (float)(gM[t] - Ss[j2] * Ss[k2] * invN);   // centered, fp32
    }
    __syncthreads();
    if (t < DIM) {
        float wf[HID];
        #pragma unroll
        for (int kk = 0; kk < HID; kk++) wf[kk] = W2[kk * DIM + t];
        double sn = 0.0;
        #pragma unroll
        for (int kk = 0; kk < HID; kk++) sn += Ss[kk] * (double)wf[kk];
        sn *= invN;
        float q0 = 0.f, q1 = 0.f, q2 = 0.f, q3 = 0.f;
        #pragma unroll
        for (int a = 0; a < HID; a++) {
            float wa = wf[a];
            #pragma unroll
            for (int b = 0; b < HID; b += 4) {
                q0 += sM[a * HID + b + 0] * (wa * wf[b + 0]);
                q1 += sM[a * HID + b + 1] * (wa * wf[b + 1]);
                q2 += sM[a * HID + b + 2] * (wa * wf[b + 2]);
                q3 += sM[a * HID + b + 3] * (wa * wf[b + 3]);
            }
        }
        float var = ((q0 + q1) + (q2 + q3)) * (float)invN;
        float scale = rsqrtf(fmaxf(var, 0.f) + BN_EPS) * gamma[t];
        gScale[t] = scale;
        gShift[t] = beta[t] - (float)sn * scale;   // b2 cancels in (h2-mean)
    }
}

// ---------------- fused: h1 = relu(bn(agg@W2)) @ W1next ---------------------
// v2: 128 threads, TWO nodes per thread -> every weight LDS is shared by two
// nodes and every serial fma2 chain is doubled (independent A/B chains).
__global__ void __launch_bounds__(FTB)
fused_bn_gemm(const float* __restrict__ agg, const float* __restrict__ W2,
              const float* __restrict__ W1n, const float* __restrict__ gScale,
              const float* __restrict__ gShift, float* __restrict__ y) {
    __shared__ __align__(16) float W2s[HID * DIM];
    __shared__ __align__(16) float W1s[DIM * HID];
    __shared__ __align__(16) float scl[DIM];
    __shared__ __align__(16) float sft[DIM];
    int t = threadIdx.x;
    for (int i = t; i < HID * DIM; i += FTB) {
        W2s[i] = W2[i];
        W1s[i] = W1n[i];
    }
    if (t < DIM) { scl[t] = gScale[t]; sft[t] = gShift[t]; }
    __syncthreads();
    int n0 = blockIdx.x * 256 + t;          // always < N_NODES (391*256 grid math)
    int n1 = n0 + FTB;
    bool has1 = (n1 < N_NODES);
    if (n0 >= N_NODES) return;
    ull aA[HID], aB[HID];
    {
        const float4* ar = reinterpret_cast<const float4*>(agg + (size_t)n0 * HID);
        #pragma unroll
        for (int k4 = 0; k4 < 4; k4++) {
            float4 v = ar[k4];
            aA[k4*4+0] = pack2(v.x, v.x);
            aA[k4*4+1] = pack2(v.y, v.y);
            aA[k4*4+2] = pack2(v.z, v.z);
            aA[k4*4+3] = pack2(v.w, v.w);
        }
        if (has1) {
            const float4* br = reinterpret_cast<const float4*>(agg + (size_t)n1 * HID);
            #pragma unroll
            for (int k4 = 0; k4 < 4; k4++) {
                float4 v = br[k4];
                aB[k4*4+0] = pack2(v.x, v.x);
                aB[k4*4+1] = pack2(v.y, v.y);
                aB[k4*4+2] = pack2(v.z, v.z);
                aB[k4*4+3] = pack2(v.w, v.w);
            }
        } else {
            #pragma unroll
            for (int k = 0; k < HID; k++) aB[k] = 0ull;
        }
    }
    ull accA[8], accB[8];
    #pragma unroll
    for (int j = 0; j < 8; j++) { accA[j] = 0ull; accB[j] = 0ull; }
    for (int cb = 0; cb < DIM; cb += 4) {
        ull tA0 = 0ull, tA1 = 0ull, tB0 = 0ull, tB1 = 0ull;
        const ulonglong2* w2p = reinterpret_cast<const ulonglong2*>(&W2s[cb]);
        #pragma unroll
        for (int k = 0; k < HID; k++) {
            ulonglong2 w = w2p[k * (DIM / 4)];
            tA0 = fma2(aA[k], w.x, tA0);
            tA1 = fma2(aA[k], w.y, tA1);
            tB0 = fma2(aB[k], w.x, tB0);
            tB1 = fma2(aB[k], w.y, tB1);
        }
        ulonglong2 sc = *reinterpret_cast<const ulonglong2*>(&scl[cb]);
        ulonglong2 sf = *reinterpret_cast<const ulonglong2*>(&sft[cb]);
        tA0 = fma2(tA0, sc.x, sf.x);
        tA1 = fma2(tA1, sc.y, sf.y);
        tB0 = fma2(tB0, sc.x, sf.x);
        tB1 = fma2(tB1, sc.y, sf.y);
        float vA[4], vB[4];
        unpack2(tA0, vA[0], vA[1]); unpack2(tA1, vA[2], vA[3]);
        unpack2(tB0, vB[0], vB[1]); unpack2(tB1, vB[2], vB[3]);
        #pragma unroll
        for (int c = 0; c < 4; c++) {
            vA[c] = fmaxf(vA[c], 0.f);
            vB[c] = fmaxf(vB[c], 0.f);
        }
        #pragma unroll
        for (int c = 0; c < 4; c++) {
            ull vAc = pack2(vA[c], vA[c]);
            ull vBc = pack2(vB[c], vB[c]);
            const ulonglong2* w1p = reinterpret_cast<const ulonglong2*>(&W1s[(cb + c) * HID]);
            #pragma unroll
            for (int p = 0; p < 4; p++) {
                ulonglong2 w = w1p[p];
                accA[p * 2 + 0] = fma2(vAc, w.x, accA[p * 2 + 0]);
                accA[p * 2 + 1] = fma2(vAc, w.y, accA[p * 2 + 1]);
                accB[p * 2 + 0] = fma2(vBc, w.x, accB[p * 2 + 0]);
                accB[p * 2 + 1] = fma2(vBc, w.y, accB[p * 2 + 1]);
            }
        }
    }
    ull* yr0 = reinterpret_cast<ull*>(y + (size_t)n0 * HID);
    #pragma unroll
    for (int j = 0; j < 8; j++) yr0[j] = accA[j];
    if (has1) {
        ull* yr1 = reinterpret_cast<ull*>(y + (size_t)n1 * HID);
        #pragma unroll
        for (int j = 0; j < 8; j++) yr1[j] = accB[j];
    }
}

// ---------------- out[N,40] = agg[N,16] @ W[16,40] + b  (f32x2 packed) ------
__global__ void out_gemm(const float* __restrict__ agg, const float* __restrict__ W,
                         const float* __restrict__ b, float* __restrict__ out) {
    __shared__ __align__(16) float Ws[HID * NCLS];
    __shared__ __align__(16) float bs[NCLS];
    for (int i = threadIdx.x; i < HID * NCLS; i += TB) Ws[i] = W[i];
    if (threadIdx.x < NCLS) bs[threadIdx.x] = b[threadIdx.x];
    __syncthreads();
    int n = blockIdx.x * TB + threadIdx.x;
    if (n >= N_NODES) return;
    ull a2[HID];
    {
        const float4* ar = reinterpret_cast<const float4*>(agg + (size_t)n * HID);
        #pragma unroll
        for (int k4 = 0; k4 < 4; k4++) {
            float4 v = ar[k4];
            a2[k4*4+0] = pack2(v.x, v.x);
            a2[k4*4+1] = pack2(v.y, v.y);
            a2[k4*4+2] = pack2(v.z, v.z);
            a2[k4*4+3] = pack2(v.w, v.w);
        }
    }
    ull o2[NCLS / 2];
    const ull* bp = reinterpret_cast<const ull*>(bs);
    #pragma unroll
    for (int p = 0; p < NCLS / 2; p++) o2[p] = bp[p];
    #pragma unroll
    for (int k = 0; k < HID; k++) {
        const ull* wr = reinterpret_cast<const ull*>(&Ws[k * NCLS]);
        #pragma unroll
        for (int p = 0; p < NCLS / 2; p++)
            o2[p] = fma2(a2[k], wr[p], o2[p]);
    }
    ull* orow = reinterpret_cast<ull*>(out + (size_t)n * NCLS);
    #pragma unroll
    for (int p = 0; p < NCLS / 2; p++) orow[p] = o2[p];
}

// ============================================================================
extern "C" void kernel_launch(void* const* d_in, const int* in_sizes, int n_in,
                              void* d_out, int out_size) {
    const float* x     = (const float*)d_in[0];
    const float* vals  = (const float*)d_in[1];
    const float* W1    = (const float*)d_in[2];   // (3,128,16)
    const float* b1    = (const float*)d_in[3];   // (3,16)
    const float* W2    = (const float*)d_in[4];   // (3,16,128)
    const float* gamma = (const float*)d_in[6];   // (3,128)
    const float* beta  = (const float*)d_in[7];   // (3,128)
    const float* W1f   = (const float*)d_in[8];   // (128,16)
    const float* b1f   = (const float*)d_in[9];   // (16,)
    const float* W2f   = (const float*)d_in[10];  // (16,40)
    const float* b2f   = (const float*)d_in[11];  // (40,)
    const int*   row   = (const int*)d_in[12];
    const int*   col   = (const int*)d_in[13];
    float* out = (float*)d_out;
    // d_in[5] (b2) cancels inside batchnorm.

    float *p_h1, *p_s1, *p_agg, *p_scale3, *p_shift3;
    double *p_M3, *p_sum3;
    unsigned int* p_cnt3;
    cudaGetSymbolAddress((void**)&p_h1,    g_h1);
    cudaGetSymbolAddress((void**)&p_s1,    g_s1);
    cudaGetSymbolAddress((void**)&p_agg,   g_agg);
    cudaGetSymbolAddress((void**)&p_M3,    g_M3);
    cudaGetSymbolAddress((void**)&p_sum3,  g_sum3);
    cudaGetSymbolAddress((void**)&p_scale3, g_scale3);
    cudaGetSymbolAddress((void**)&p_shift3, g_shift3);
    cudaGetSymbolAddress((void**)&p_cnt3,  g_cnt3);

    prolog_kernel<<<NODE_BLK + RP_BLK, TB>>>(row, x, W1, p_h1);

    for (int i = 0; i < 3; i++) {
        double* gM = p_M3 + (size_t)i * HID * HID;
        double* gS = p_sum3 + (size_t)i * HID;
        float* gScale = p_scale3 + (size_t)i * DIM;
        float* gShift = p_shift3 + (size_t)i * DIM;
        const float* W2L = W2 + (size_t)i * HID * DIM;
        const float* Wnext = (i < 2) ? (W1 + (size_t)(i + 1) * DIM * HID) : W1f;

        spmm16<true, false><<<SPMM_BLK, TB>>>(p_h1, vals, col, b1 + i * HID, p_s1,
                                              nullptr, nullptr, nullptr, nullptr,
                                              nullptr, nullptr, nullptr, nullptr);
        spmm16<false, true><<<STATS_BLK, TB>>>(p_s1, vals, col, nullptr, p_agg,
                                               gM, gS, W2L, gamma + i * DIM,
                                               beta + i * DIM, gScale, gShift,
                                               p_cnt3 + i);
        fused_bn_gemm<<<FUSED_BLK, FTB>>>(p_agg, W2L, Wnext, gScale, gShift, p_h1);
    }

    spmm16<true, false><<<SPMM_BLK, TB>>>(p_h1, vals, col, b1f, p_s1,
                                          nullptr, nullptr, nullptr, nullptr,
                                          nullptr, nullptr, nullptr, nullptr);
    spmm16<false, false><<<SPMM_BLK, TB>>>(p_s1, vals, col, nullptr, p_agg,
                                           nullptr, nullptr, nullptr, nullptr,
                                           nullptr, nullptr, nullptr, nullptr);
    out_gemm<<<NODE_BLK, TB>>>(p_agg, W2f, b2f, out);
}